// round 1
// baseline (speedup 1.0000x reference)
#include <cuda_runtime.h>

#define B_ 2
#define S_ 2048
#define D_ 768
#define H_ 12
#define DK_ 64
#define R_ 8
#define N_ 4096   // B_*S_

// ---------------- scratch (static device globals; no allocation) ----------------
__device__ float g_Aq[N_ * R_];
__device__ float g_Av[N_ * R_];
__device__ float g_Qadj[(size_t)N_ * D_];
__device__ float g_Vadj[(size_t)N_ * D_];
__device__ float g_qh[(size_t)N_ * D_];   // [B,H,S,DK], pre-scaled by 1/8
__device__ float g_kh[(size_t)N_ * D_];   // [B,H,S,DK]
__device__ float g_vh[(size_t)N_ * D_];   // [B,H,S,DK]
__device__ float g_ao[(size_t)N_ * D_];   // [B,S,D] attention output

// ---------------- K0: x[N,768] @ A[768,8] -> out[N,8]  (one warp per row) ------
__global__ void lora_down_kernel(const float* __restrict__ x,
                                 const float* __restrict__ A,
                                 float* __restrict__ out) {
    int warp = (blockIdx.x * blockDim.x + threadIdx.x) >> 5;
    int lane = threadIdx.x & 31;
    if (warp >= N_) return;
    float acc[8] = {0.f,0.f,0.f,0.f,0.f,0.f,0.f,0.f};
    const float* xr = x + (size_t)warp * D_;
    for (int k = lane; k < D_; k += 32) {
        float xv = xr[k];
        float4 a0 = *(const float4*)(A + k * 8);
        float4 a1 = *(const float4*)(A + k * 8 + 4);
        acc[0] += xv * a0.x; acc[1] += xv * a0.y; acc[2] += xv * a0.z; acc[3] += xv * a0.w;
        acc[4] += xv * a1.x; acc[5] += xv * a1.y; acc[6] += xv * a1.z; acc[7] += xv * a1.w;
    }
    #pragma unroll
    for (int r = 0; r < 8; r++) {
        #pragma unroll
        for (int off = 16; off > 0; off >>= 1)
            acc[r] += __shfl_xor_sync(0xffffffffu, acc[r], off);
    }
    if (lane == 0) {
        float4* o = (float4*)(out + (size_t)warp * 8);
        o[0] = make_float4(acc[0], acc[1], acc[2], acc[3]);
        o[1] = make_float4(acc[4], acc[5], acc[6], acc[7]);
    }
}

// -------- K1: out = x + Ar[N,8] @ Bm[8,768]  (elementwise, one thread/elem) ----
__global__ void lora_up_kernel(const float* __restrict__ x,
                               const float* __restrict__ Ar,
                               const float* __restrict__ Bm,
                               float* __restrict__ out) {
    int i = blockIdx.x * blockDim.x + threadIdx.x;   // grid exactly N_*D_
    int row = i / D_;
    int col = i - row * D_;
    float4 a0 = *(const float4*)(Ar + (size_t)row * 8);
    float4 a1 = *(const float4*)(Ar + (size_t)row * 8 + 4);
    float s = x[i];
    s += a0.x * Bm[0 * D_ + col];
    s += a0.y * Bm[1 * D_ + col];
    s += a0.z * Bm[2 * D_ + col];
    s += a0.w * Bm[3 * D_ + col];
    s += a1.x * Bm[4 * D_ + col];
    s += a1.y * Bm[5 * D_ + col];
    s += a1.z * Bm[6 * D_ + col];
    s += a1.w * Bm[7 * D_ + col];
    out[i] = s;
}

// ---- K2: C[i,j] = scale*( sum_k A[i,k]*W[j,k] + bias[j] )  BM=128 BN=64 BK=16 --
// headPermute: write C as [B,H,S,DK] instead of [N,D].
__global__ void __launch_bounds__(256)
gemm_nt_kernel(const float* __restrict__ A, const float* __restrict__ W,
               const float* __restrict__ bias, float* __restrict__ C,
               float scale, int headPermute) {
    __shared__ float As[16][128];
    __shared__ float Bs[16][64];
    int tid = threadIdx.x;
    int ty = tid >> 4, tx = tid & 15;
    int i0 = blockIdx.x * 128;
    int n0 = blockIdx.y * 64;
    float c[8][4];
    #pragma unroll
    for (int ii = 0; ii < 8; ii++)
        #pragma unroll
        for (int jj = 0; jj < 4; jj++) c[ii][jj] = 0.f;

    for (int k0 = 0; k0 < D_; k0 += 16) {
        #pragma unroll
        for (int p = 0; p < 2; p++) {
            int li = tid + p * 256;
            int row = li >> 2, kc = (li & 3) << 2;
            float4 v = *(const float4*)(A + (size_t)(i0 + row) * D_ + k0 + kc);
            As[kc + 0][row] = v.x; As[kc + 1][row] = v.y;
            As[kc + 2][row] = v.z; As[kc + 3][row] = v.w;
        }
        {
            int n = tid >> 2, kc = (tid & 3) << 2;
            float4 v = *(const float4*)(W + (size_t)(n0 + n) * D_ + k0 + kc);
            Bs[kc + 0][n] = v.x; Bs[kc + 1][n] = v.y;
            Bs[kc + 2][n] = v.z; Bs[kc + 3][n] = v.w;
        }
        __syncthreads();
        #pragma unroll
        for (int k = 0; k < 16; k++) {
            float4 a0 = *(const float4*)&As[k][ty * 8];
            float4 a1 = *(const float4*)&As[k][ty * 8 + 4];
            float4 b4 = *(const float4*)&Bs[k][tx * 4];
            float ar[8] = {a0.x, a0.y, a0.z, a0.w, a1.x, a1.y, a1.z, a1.w};
            float br[4] = {b4.x, b4.y, b4.z, b4.w};
            #pragma unroll
            for (int ii = 0; ii < 8; ii++)
                #pragma unroll
                for (int jj = 0; jj < 4; jj++)
                    c[ii][jj] += ar[ii] * br[jj];
        }
        __syncthreads();
    }

    int j0 = n0 + tx * 4;
    float4 bv = *(const float4*)(bias + j0);
    float bb[4] = {bv.x, bv.y, bv.z, bv.w};
    #pragma unroll
    for (int ii = 0; ii < 8; ii++) {
        int i = i0 + ty * 8 + ii;
        float4 o;
        o.x = scale * (c[ii][0] + bb[0]);
        o.y = scale * (c[ii][1] + bb[1]);
        o.z = scale * (c[ii][2] + bb[2]);
        o.w = scale * (c[ii][3] + bb[3]);
        if (headPermute) {
            int b = i >> 11, s = i & 2047;
            int h = j0 >> 6, dk = j0 & 63;
            *(float4*)(C + (((size_t)(b * H_ + h)) * S_ + s) * DK_ + dk) = o;
        } else {
            *(float4*)(C + (size_t)i * D_ + j0) = o;
        }
    }
}

// ---------------- K3: flash attention, BM=BN=64, DK=64, fp32 -------------------
#define KST 68   // padded K-tile stride (2-way max conflict, keeps 16B alignment)
#define ATTN_SMEM ((64*64 + 64*KST + 64*64 + 64*64) * 4)

__global__ void __launch_bounds__(256)
attn_kernel(const int* __restrict__ mask, float* __restrict__ out) {
    extern __shared__ float sm[];
    float* Qs = sm;                     // [64][64]
    float* Ks = Qs + 64 * 64;           // [64][KST]
    float* Vs = Ks + 64 * KST;          // [64][64]
    float* Ps = Vs + 64 * 64;           // [64][64]

    int tid = threadIdx.x;
    int ty = tid >> 4, tx = tid & 15;
    int rm = ty * 4;
    int qb = blockIdx.x, h = blockIdx.y, b = blockIdx.z;
    int bh = b * H_ + h;
    int q0 = qb * 64;

    const float* qg = g_qh + ((size_t)bh * S_ + q0) * DK_;
    const float* kg = g_kh + (size_t)bh * S_ * DK_;
    const float* vg = g_vh + (size_t)bh * S_ * DK_;
    const int* mrow = mask + ((size_t)b * S_ + q0) * S_;

    #pragma unroll
    for (int p = 0; p < 4; p++) {
        int li = tid + p * 256;
        int row = li >> 4, d0 = (li & 15) << 2;
        *(float4*)(Qs + row * 64 + d0) = *(const float4*)(qg + (size_t)row * DK_ + d0);
    }

    float m[4], l[4], acc[4][4];
    #pragma unroll
    for (int ii = 0; ii < 4; ii++) {
        m[ii] = -1e30f; l[ii] = 0.f;
        #pragma unroll
        for (int jj = 0; jj < 4; jj++) acc[ii][jj] = 0.f;
    }

    for (int kb = 0; kb < S_ / 64; kb++) {
        int k0 = kb * 64;
        __syncthreads();   // protect Ks/Vs reuse
        #pragma unroll
        for (int p = 0; p < 4; p++) {
            int li = tid + p * 256;
            int row = li >> 4, d0 = (li & 15) << 2;
            float4 kv = *(const float4*)(kg + (size_t)(k0 + row) * DK_ + d0);
            *(float4*)(Ks + row * KST + d0) = kv;
            float4 vv = *(const float4*)(vg + (size_t)(k0 + row) * DK_ + d0);
            *(float4*)(Vs + row * 64 + d0) = vv;
        }
        __syncthreads();

        // --- QK^T tile (q pre-scaled by 1/8) ---
        float s[4][4];
        #pragma unroll
        for (int ii = 0; ii < 4; ii++)
            #pragma unroll
            for (int jj = 0; jj < 4; jj++) s[ii][jj] = 0.f;

        for (int d = 0; d < 64; d += 4) {
            float4 q4[4], k4[4];
            #pragma unroll
            for (int ii = 0; ii < 4; ii++) q4[ii] = *(const float4*)(Qs + (rm + ii) * 64 + d);
            #pragma unroll
            for (int jj = 0; jj < 4; jj++) k4[jj] = *(const float4*)(Ks + (tx * 4 + jj) * KST + d);
            #pragma unroll
            for (int ii = 0; ii < 4; ii++)
                #pragma unroll
                for (int jj = 0; jj < 4; jj++) {
                    s[ii][jj] += q4[ii].x * k4[jj].x;
                    s[ii][jj] += q4[ii].y * k4[jj].y;
                    s[ii][jj] += q4[ii].z * k4[jj].z;
                    s[ii][jj] += q4[ii].w * k4[jj].w;
                }
        }

        // --- mask + online softmax update ---
        #pragma unroll
        for (int ii = 0; ii < 4; ii++) {
            int4 mk = *(const int4*)(mrow + (size_t)(rm + ii) * S_ + k0 + tx * 4);
            if (mk.x == 0) s[ii][0] = -1e9f;
            if (mk.y == 0) s[ii][1] = -1e9f;
            if (mk.z == 0) s[ii][2] = -1e9f;
            if (mk.w == 0) s[ii][3] = -1e9f;

            float rmax = fmaxf(fmaxf(s[ii][0], s[ii][1]), fmaxf(s[ii][2], s[ii][3]));
            #pragma unroll
            for (int off = 8; off > 0; off >>= 1)
                rmax = fmaxf(rmax, __shfl_xor_sync(0xffffffffu, rmax, off));

            float mn = fmaxf(m[ii], rmax);
            float corr = __expf(m[ii] - mn);
            float p0 = __expf(s[ii][0] - mn);
            float p1 = __expf(s[ii][1] - mn);
            float p2 = __expf(s[ii][2] - mn);
            float p3 = __expf(s[ii][3] - mn);
            float rs = p0 + p1 + p2 + p3;
            #pragma unroll
            for (int off = 8; off > 0; off >>= 1)
                rs += __shfl_xor_sync(0xffffffffu, rs, off);

            l[ii] = l[ii] * corr + rs;
            m[ii] = mn;
            acc[ii][0] *= corr; acc[ii][1] *= corr;
            acc[ii][2] *= corr; acc[ii][3] *= corr;

            float* pr = Ps + (rm + ii) * 64 + tx * 4;
            pr[0] = p0; pr[1] = p1; pr[2] = p2; pr[3] = p3;
        }
        __syncwarp();   // Ps producer/consumer are the same 16-lane group; order within warp

        // --- acc += P @ V ---
        for (int kk = 0; kk < 64; kk += 4) {
            float4 p4[4];
            #pragma unroll
            for (int ii = 0; ii < 4; ii++) p4[ii] = *(const float4*)(Ps + (rm + ii) * 64 + kk);
            float vr[4][4];
            #pragma unroll
            for (int t = 0; t < 4; t++) {
                float4 v4 = *(const float4*)(Vs + (kk + t) * 64 + tx * 4);
                vr[t][0] = v4.x; vr[t][1] = v4.y; vr[t][2] = v4.z; vr[t][3] = v4.w;
            }
            #pragma unroll
            for (int ii = 0; ii < 4; ii++) {
                float pa[4] = {p4[ii].x, p4[ii].y, p4[ii].z, p4[ii].w};
                #pragma unroll
                for (int jj = 0; jj < 4; jj++) {
                    acc[ii][jj] += pa[0] * vr[0][jj];
                    acc[ii][jj] += pa[1] * vr[1][jj];
                    acc[ii][jj] += pa[2] * vr[2][jj];
                    acc[ii][jj] += pa[3] * vr[3][jj];
                }
            }
        }
    }

    #pragma unroll
    for (int ii = 0; ii < 4; ii++) {
        float inv = 1.0f / l[ii];
        int s_idx = q0 + rm + ii;
        float4 o = make_float4(acc[ii][0] * inv, acc[ii][1] * inv,
                               acc[ii][2] * inv, acc[ii][3] * inv);
        *(float4*)(out + ((size_t)(b * S_ + s_idx)) * D_ + h * DK_ + tx * 4) = o;
    }
}

// --------------------------------- host ----------------------------------------
extern "C" void kernel_launch(void* const* d_in, const int* in_sizes, int n_in,
                              void* d_out, int out_size) {
    const float* query = (const float*)d_in[0];
    const float* key   = (const float*)d_in[1];
    const float* value = (const float*)d_in[2];
    const int*   mask  = (const int*)d_in[3];
    const float* lAq   = (const float*)d_in[4];
    const float* lBq   = (const float*)d_in[5];
    const float* lAv   = (const float*)d_in[6];
    const float* lBv   = (const float*)d_in[7];
    const float* Wq    = (const float*)d_in[8];
    const float* bq    = (const float*)d_in[9];
    const float* Wk    = (const float*)d_in[10];
    const float* bk    = (const float*)d_in[11];
    const float* Wv    = (const float*)d_in[12];
    const float* bv    = (const float*)d_in[13];
    const float* Wm    = (const float*)d_in[14];
    const float* bm    = (const float*)d_in[15];
    float* out = (float*)d_out;

    void *pAq, *pAv, *pQadj, *pVadj, *pqh, *pkh, *pvh, *pao;
    cudaGetSymbolAddress(&pAq,   g_Aq);
    cudaGetSymbolAddress(&pAv,   g_Av);
    cudaGetSymbolAddress(&pQadj, g_Qadj);
    cudaGetSymbolAddress(&pVadj, g_Vadj);
    cudaGetSymbolAddress(&pqh,   g_qh);
    cudaGetSymbolAddress(&pkh,   g_kh);
    cudaGetSymbolAddress(&pvh,   g_vh);
    cudaGetSymbolAddress(&pao,   g_ao);

    // LoRA down: [N,768]@[768,8]
    lora_down_kernel<<<N_ / 8, 256>>>(query, lAq, (float*)pAq);
    lora_down_kernel<<<N_ / 8, 256>>>(value, lAv, (float*)pAv);

    // LoRA up + residual
    lora_up_kernel<<<(N_ * D_) / 256, 256>>>(query, (const float*)pAq, lBq, (float*)pQadj);
    lora_up_kernel<<<(N_ * D_) / 256, 256>>>(value, (const float*)pAv, lBv, (float*)pVadj);

    // Projections (note the reference's stream swap):
    //   v = heads(Qadj @ Wv^T + bv), k = heads(key @ Wk^T + bk),
    //   q = heads(Vadj @ Wq^T + bq) * (1/sqrt(DK))
    dim3 gg(N_ / 128, D_ / 64);
    gemm_nt_kernel<<<gg, 256>>>((const float*)pQadj, Wv, bv, (float*)pvh, 1.0f,   1);
    gemm_nt_kernel<<<gg, 256>>>(key,                 Wk, bk, (float*)pkh, 1.0f,   1);
    gemm_nt_kernel<<<gg, 256>>>((const float*)pVadj, Wq, bq, (float*)pqh, 0.125f, 1);

    // Flash attention -> g_ao [B,S,D]
    cudaFuncSetAttribute(attn_kernel, cudaFuncAttributeMaxDynamicSharedMemorySize, ATTN_SMEM);
    attn_kernel<<<dim3(S_ / 64, H_, B_), 256, ATTN_SMEM>>>(mask, (float*)pao);

    // Final: out = g_ao @ Wm^T + bm
    gemm_nt_kernel<<<gg, 256>>>((const float*)pao, Wm, bm, out, 1.0f, 0);
}

// round 2
// speedup vs baseline: 3.3514x; 3.3514x over previous
#include <cuda_runtime.h>

#define B_ 2
#define S_ 2048
#define D_ 768
#define H_ 12
#define DK_ 64
#define R_ 8
#define N_ 4096   // B_*S_

// ---------------- scratch (static device globals; no allocation) ----------------
__device__ float g_Aq[N_ * R_];
__device__ float g_Av[N_ * R_];
__device__ float g_Qadj[(size_t)N_ * D_];
__device__ float g_Vadj[(size_t)N_ * D_];
__device__ float g_qh[(size_t)N_ * D_];   // [B,H,S,DK], pre-scaled by 1/8
__device__ float g_kh[(size_t)N_ * D_];   // [B,H,S,DK]
__device__ float g_vh[(size_t)N_ * D_];   // [B,H,S,DK]
__device__ float g_ao[(size_t)N_ * D_];   // [B,S,D] attention output
__device__ unsigned g_mw[B_ * S_ * (S_ / 32)];  // packed mask bits

// ---------------- tf32 helpers --------------------------------------------------
__device__ __forceinline__ unsigned f2tf(float f) {
    unsigned u;
    asm("cvt.rna.tf32.f32 %0, %1;" : "=r"(u) : "f"(f));
    return u;
}
__device__ __forceinline__ uint4 cvt4(float4 v) {
    return make_uint4(f2tf(v.x), f2tf(v.y), f2tf(v.z), f2tf(v.w));
}
// D += A(16x8,row) * B(8x8,col)  tf32 -> f32
__device__ __forceinline__ void mma8(float* c, const unsigned* a, const unsigned* b) {
    asm volatile(
        "mma.sync.aligned.m16n8k8.row.col.f32.tf32.tf32.f32 "
        "{%0,%1,%2,%3}, {%4,%5,%6,%7}, {%8,%9}, {%0,%1,%2,%3};"
        : "+f"(c[0]), "+f"(c[1]), "+f"(c[2]), "+f"(c[3])
        : "r"(a[0]), "r"(a[1]), "r"(a[2]), "r"(a[3]), "r"(b[0]), "r"(b[1]));
}

// ---------------- K0: x[N,768] @ A[768,8] -> out[N,8]  (one warp per row) ------
__global__ void lora_down_kernel(const float* __restrict__ x,
                                 const float* __restrict__ A,
                                 float* __restrict__ out) {
    int warp = (blockIdx.x * blockDim.x + threadIdx.x) >> 5;
    int lane = threadIdx.x & 31;
    if (warp >= N_) return;
    float acc[8] = {0.f,0.f,0.f,0.f,0.f,0.f,0.f,0.f};
    const float* xr = x + (size_t)warp * D_;
    for (int k = lane; k < D_; k += 32) {
        float xv = xr[k];
        float4 a0 = *(const float4*)(A + k * 8);
        float4 a1 = *(const float4*)(A + k * 8 + 4);
        acc[0] += xv * a0.x; acc[1] += xv * a0.y; acc[2] += xv * a0.z; acc[3] += xv * a0.w;
        acc[4] += xv * a1.x; acc[5] += xv * a1.y; acc[6] += xv * a1.z; acc[7] += xv * a1.w;
    }
    #pragma unroll
    for (int r = 0; r < 8; r++) {
        #pragma unroll
        for (int off = 16; off > 0; off >>= 1)
            acc[r] += __shfl_xor_sync(0xffffffffu, acc[r], off);
    }
    if (lane == 0) {
        float4* o = (float4*)(out + (size_t)warp * 8);
        o[0] = make_float4(acc[0], acc[1], acc[2], acc[3]);
        o[1] = make_float4(acc[4], acc[5], acc[6], acc[7]);
    }
}

// -------- K1: out = x + Ar[N,8] @ Bm[8,768]  ------------------------------------
__global__ void lora_up_kernel(const float* __restrict__ x,
                               const float* __restrict__ Ar,
                               const float* __restrict__ Bm,
                               float* __restrict__ out) {
    int i = blockIdx.x * blockDim.x + threadIdx.x;
    int row = i / D_;
    int col = i - row * D_;
    float4 a0 = *(const float4*)(Ar + (size_t)row * 8);
    float4 a1 = *(const float4*)(Ar + (size_t)row * 8 + 4);
    float s = x[i];
    s += a0.x * Bm[0 * D_ + col];
    s += a0.y * Bm[1 * D_ + col];
    s += a0.z * Bm[2 * D_ + col];
    s += a0.w * Bm[3 * D_ + col];
    s += a1.x * Bm[4 * D_ + col];
    s += a1.y * Bm[5 * D_ + col];
    s += a1.z * Bm[6 * D_ + col];
    s += a1.w * Bm[7 * D_ + col];
    out[i] = s;
}

// -------- K1b: pack mask ints into bits: g_mw[b*S + q][S/32] --------------------
__global__ void mask_pack_kernel(const int* __restrict__ mask,
                                 unsigned* __restrict__ mw) {
    int w = blockIdx.x * blockDim.x + threadIdx.x;   // grid exactly B_*S_*S_/32
    const int4* mp = (const int4*)(mask + (size_t)w * 32);
    unsigned bits = 0;
    #pragma unroll
    for (int j = 0; j < 8; j++) {
        int4 v = mp[j];
        bits |= (v.x != 0 ? 1u : 0u) << (j * 4 + 0);
        bits |= (v.y != 0 ? 1u : 0u) << (j * 4 + 1);
        bits |= (v.z != 0 ? 1u : 0u) << (j * 4 + 2);
        bits |= (v.w != 0 ? 1u : 0u) << (j * 4 + 3);
    }
    mw[w] = bits;
}

// ---- K2: tf32 tensor-core GEMM  C = scale*(A @ W^T + bias)  --------------------
// BM=128, BN=64, BK=32; 128 threads = 4 warps (2m x 2n), warp tile 64x32.
#define GPAD 36
__global__ void __launch_bounds__(128)
gemm_tf32_kernel(const float* __restrict__ A, const float* __restrict__ W,
                 const float* __restrict__ bias, float* __restrict__ C,
                 float scale, int headPermute) {
    __shared__ unsigned As[128 * GPAD];
    __shared__ unsigned Bs[64 * GPAD];
    int tid = threadIdx.x;
    int warp = tid >> 5, lane = tid & 31;
    int wm = warp >> 1, wn = warp & 1;
    int lr = lane >> 2, lc = lane & 3;
    int i0 = blockIdx.x * 128, n0 = blockIdx.y * 64;

    float c[4][4][4];
    #pragma unroll
    for (int mi = 0; mi < 4; mi++)
        #pragma unroll
        for (int ni = 0; ni < 4; ni++)
            #pragma unroll
            for (int q = 0; q < 4; q++) c[mi][ni][q] = 0.f;

    for (int k0 = 0; k0 < D_; k0 += 32) {
        #pragma unroll
        for (int p = 0; p < 8; p++) {
            int f = tid + p * 128;
            int row = f >> 3, cc = (f & 7) << 2;
            float4 v = *(const float4*)(A + (size_t)(i0 + row) * D_ + k0 + cc);
            *(uint4*)&As[row * GPAD + cc] = cvt4(v);
        }
        #pragma unroll
        for (int p = 0; p < 4; p++) {
            int f = tid + p * 128;
            int row = f >> 3, cc = (f & 7) << 2;
            float4 v = *(const float4*)(W + (size_t)(n0 + row) * D_ + k0 + cc);
            *(uint4*)&Bs[row * GPAD + cc] = cvt4(v);
        }
        __syncthreads();
        #pragma unroll
        for (int kk = 0; kk < 32; kk += 8) {
            unsigned a[4][4], bf[4][2];
            #pragma unroll
            for (int mi = 0; mi < 4; mi++) {
                int r = wm * 64 + mi * 16 + lr;
                a[mi][0] = As[r * GPAD + kk + lc];
                a[mi][1] = As[(r + 8) * GPAD + kk + lc];
                a[mi][2] = As[r * GPAD + kk + lc + 4];
                a[mi][3] = As[(r + 8) * GPAD + kk + lc + 4];
            }
            #pragma unroll
            for (int ni = 0; ni < 4; ni++) {
                int n = wn * 32 + ni * 8 + lr;
                bf[ni][0] = Bs[n * GPAD + kk + lc];
                bf[ni][1] = Bs[n * GPAD + kk + lc + 4];
            }
            #pragma unroll
            for (int mi = 0; mi < 4; mi++)
                #pragma unroll
                for (int ni = 0; ni < 4; ni++)
                    mma8(c[mi][ni], a[mi], bf[ni]);
        }
        __syncthreads();
    }

    #pragma unroll
    for (int mi = 0; mi < 4; mi++) {
        #pragma unroll
        for (int ni = 0; ni < 4; ni++) {
            int i = i0 + wm * 64 + mi * 16 + lr;
            int j = n0 + wn * 32 + ni * 8 + 2 * lc;
            float b0 = bias[j], b1 = bias[j + 1];
            float2 o0 = make_float2(scale * (c[mi][ni][0] + b0), scale * (c[mi][ni][1] + b1));
            float2 o1 = make_float2(scale * (c[mi][ni][2] + b0), scale * (c[mi][ni][3] + b1));
            if (headPermute) {
                int bb = i >> 11, s = i & 2047;
                int hh = j >> 6, dk = j & 63;
                *(float2*)(C + (((size_t)(bb * H_ + hh)) * S_ + s) * DK_ + dk) = o0;
                *(float2*)(C + (((size_t)(bb * H_ + hh)) * S_ + (s + 8)) * DK_ + dk) = o1;
            } else {
                *(float2*)(C + (size_t)i * D_ + j) = o0;
                *(float2*)(C + (size_t)(i + 8) * D_ + j) = o1;
            }
        }
    }
}

// ---------------- K3: flash attention with tf32 mma -----------------------------
// BM=128 q rows, KV tile 64, DK=64. 128 threads = 4 warps, warp strip = 32 rows.
#define APAD 68
#define ATTN_SMEM ((128 * APAD + 64 * APAD + 64 * APAD + 128 * APAD) * 4)

__global__ void __launch_bounds__(128)
attn_tc_kernel(const unsigned* __restrict__ mw, float* __restrict__ out) {
    extern __shared__ unsigned sm[];
    unsigned* Qs = sm;                   // [128][APAD]
    unsigned* Ks = Qs + 128 * APAD;      // [64][APAD]
    unsigned* Vs = Ks + 64 * APAD;       // [64][APAD]
    unsigned* Ps = Vs + 64 * APAD;       // [128][APAD]

    int tid = threadIdx.x, warp = tid >> 5, lane = tid & 31;
    int lr = lane >> 2, lc = lane & 3;
    int qb = blockIdx.x, h = blockIdx.y, b = blockIdx.z;
    int q0 = qb * 128, bh = b * H_ + h;

    const float* qg = g_qh + ((size_t)bh * S_ + q0) * DK_;
    const float* kg = g_kh + (size_t)bh * S_ * DK_;
    const float* vg = g_vh + (size_t)bh * S_ * DK_;

    #pragma unroll
    for (int p = 0; p < 16; p++) {
        int f = tid + p * 128;
        int row = f >> 4, cc = (f & 15) << 2;
        *(uint4*)&Qs[row * APAD + cc] = cvt4(*(const float4*)(qg + (size_t)row * DK_ + cc));
    }

    float o[2][8][4];
    float m[2][2], l[2][2];
    #pragma unroll
    for (int mi = 0; mi < 2; mi++) {
        m[mi][0] = -1e30f; m[mi][1] = -1e30f;
        l[mi][0] = 0.f;    l[mi][1] = 0.f;
        #pragma unroll
        for (int ni = 0; ni < 8; ni++)
            #pragma unroll
            for (int q = 0; q < 4; q++) o[mi][ni][q] = 0.f;
    }

    for (int kb = 0; kb < S_ / 64; kb++) {
        int k0 = kb * 64;
        __syncthreads();
        #pragma unroll
        for (int p = 0; p < 8; p++) {
            int f = tid + p * 128;
            int row = f >> 4, cc = (f & 15) << 2;
            *(uint4*)&Ks[row * APAD + cc] = cvt4(*(const float4*)(kg + (size_t)(k0 + row) * DK_ + cc));
            *(uint4*)&Vs[row * APAD + cc] = cvt4(*(const float4*)(vg + (size_t)(k0 + row) * DK_ + cc));
        }
        __syncthreads();

        // --- S = Q K^T (q pre-scaled by 1/8) ---
        float s[2][8][4];
        #pragma unroll
        for (int mi = 0; mi < 2; mi++)
            #pragma unroll
            for (int ni = 0; ni < 8; ni++)
                #pragma unroll
                for (int q = 0; q < 4; q++) s[mi][ni][q] = 0.f;

        #pragma unroll
        for (int kk = 0; kk < 64; kk += 8) {
            unsigned a[2][4], bf[8][2];
            #pragma unroll
            for (int mi = 0; mi < 2; mi++) {
                int r = warp * 32 + mi * 16 + lr;
                a[mi][0] = Qs[r * APAD + kk + lc];
                a[mi][1] = Qs[(r + 8) * APAD + kk + lc];
                a[mi][2] = Qs[r * APAD + kk + lc + 4];
                a[mi][3] = Qs[(r + 8) * APAD + kk + lc + 4];
            }
            #pragma unroll
            for (int ni = 0; ni < 8; ni++) {
                int n = ni * 8 + lr;
                bf[ni][0] = Ks[n * APAD + kk + lc];
                bf[ni][1] = Ks[n * APAD + kk + lc + 4];
            }
            #pragma unroll
            for (int mi = 0; mi < 2; mi++)
                #pragma unroll
                for (int ni = 0; ni < 8; ni++)
                    mma8(s[mi][ni], a[mi], bf[ni]);
        }

        // --- mask + online softmax + write P (tf32) to smem ---
        #pragma unroll
        for (int mi = 0; mi < 2; mi++) {
            #pragma unroll
            for (int hh = 0; hh < 2; hh++) {
                int rloc = warp * 32 + mi * 16 + lr + hh * 8;
                int grow = q0 + rloc;
                uint2 w = *(const uint2*)(mw + ((size_t)b * S_ + grow) * (S_ / 32) + kb * 2);
                float rmax = -1e30f;
                #pragma unroll
                for (int ni = 0; ni < 8; ni++) {
                    int col = ni * 8 + 2 * lc;
                    unsigned ws = (col < 32) ? w.x : w.y;
                    int bit = col & 31;
                    float* sp = &s[mi][ni][hh * 2];
                    if (!((ws >> bit) & 1u))       sp[0] = -1e9f;
                    if (!((ws >> (bit + 1)) & 1u)) sp[1] = -1e9f;
                    rmax = fmaxf(rmax, fmaxf(sp[0], sp[1]));
                }
                rmax = fmaxf(rmax, __shfl_xor_sync(0xffffffffu, rmax, 1));
                rmax = fmaxf(rmax, __shfl_xor_sync(0xffffffffu, rmax, 2));
                float mn = fmaxf(m[mi][hh], rmax);
                float corr = __expf(m[mi][hh] - mn);
                m[mi][hh] = mn;
                float rs = 0.f;
                #pragma unroll
                for (int ni = 0; ni < 8; ni++) {
                    float* sp = &s[mi][ni][hh * 2];
                    float p0 = __expf(sp[0] - mn);
                    float p1 = __expf(sp[1] - mn);
                    rs += p0 + p1;
                    int col = ni * 8 + 2 * lc;
                    *(uint2*)&Ps[rloc * APAD + col] = make_uint2(f2tf(p0), f2tf(p1));
                    o[mi][ni][hh * 2]     *= corr;
                    o[mi][ni][hh * 2 + 1] *= corr;
                }
                rs += __shfl_xor_sync(0xffffffffu, rs, 1);
                rs += __shfl_xor_sync(0xffffffffu, rs, 2);
                l[mi][hh] = l[mi][hh] * corr + rs;
            }
        }
        __syncwarp();   // P rows are warp-private; order STS before LDS within warp

        // --- O += P @ V ---
        #pragma unroll
        for (int kk = 0; kk < 64; kk += 8) {
            unsigned a[2][4], bf[8][2];
            #pragma unroll
            for (int mi = 0; mi < 2; mi++) {
                int r = warp * 32 + mi * 16 + lr;
                a[mi][0] = Ps[r * APAD + kk + lc];
                a[mi][1] = Ps[(r + 8) * APAD + kk + lc];
                a[mi][2] = Ps[r * APAD + kk + lc + 4];
                a[mi][3] = Ps[(r + 8) * APAD + kk + lc + 4];
            }
            #pragma unroll
            for (int ni = 0; ni < 8; ni++) {
                int n = ni * 8 + lr;
                bf[ni][0] = Vs[(kk + lc) * APAD + n];
                bf[ni][1] = Vs[(kk + lc + 4) * APAD + n];
            }
            #pragma unroll
            for (int mi = 0; mi < 2; mi++)
                #pragma unroll
                for (int ni = 0; ni < 8; ni++)
                    mma8(o[mi][ni], a[mi], bf[ni]);
        }
    }

    // --- epilogue: O / l -> g_ao [B,S,D] ---
    #pragma unroll
    for (int mi = 0; mi < 2; mi++) {
        #pragma unroll
        for (int hh = 0; hh < 2; hh++) {
            float inv = 1.0f / l[mi][hh];
            int grow = q0 + warp * 32 + mi * 16 + lr + hh * 8;
            #pragma unroll
            for (int ni = 0; ni < 8; ni++) {
                int col = ni * 8 + 2 * lc;
                float2 ov = make_float2(o[mi][ni][hh * 2] * inv,
                                        o[mi][ni][hh * 2 + 1] * inv);
                *(float2*)(out + ((size_t)(b * S_ + grow)) * D_ + h * DK_ + col) = ov;
            }
        }
    }
}

// --------------------------------- host ----------------------------------------
extern "C" void kernel_launch(void* const* d_in, const int* in_sizes, int n_in,
                              void* d_out, int out_size) {
    const float* query = (const float*)d_in[0];
    const float* key   = (const float*)d_in[1];
    const float* value = (const float*)d_in[2];
    const int*   mask  = (const int*)d_in[3];
    const float* lAq   = (const float*)d_in[4];
    const float* lBq   = (const float*)d_in[5];
    const float* lAv   = (const float*)d_in[6];
    const float* lBv   = (const float*)d_in[7];
    const float* Wq    = (const float*)d_in[8];
    const float* bq    = (const float*)d_in[9];
    const float* Wk    = (const float*)d_in[10];
    const float* bk    = (const float*)d_in[11];
    const float* Wv    = (const float*)d_in[12];
    const float* bv    = (const float*)d_in[13];
    const float* Wm    = (const float*)d_in[14];
    const float* bm    = (const float*)d_in[15];
    float* out = (float*)d_out;

    void *pAq, *pAv, *pQadj, *pVadj, *pqh, *pkh, *pvh, *pao, *pmw;
    cudaGetSymbolAddress(&pAq,   g_Aq);
    cudaGetSymbolAddress(&pAv,   g_Av);
    cudaGetSymbolAddress(&pQadj, g_Qadj);
    cudaGetSymbolAddress(&pVadj, g_Vadj);
    cudaGetSymbolAddress(&pqh,   g_qh);
    cudaGetSymbolAddress(&pkh,   g_kh);
    cudaGetSymbolAddress(&pvh,   g_vh);
    cudaGetSymbolAddress(&pao,   g_ao);
    cudaGetSymbolAddress(&pmw,   g_mw);

    // mask pack (independent, kick off first)
    mask_pack_kernel<<<(B_ * S_ * (S_ / 32)) / 256, 256>>>(mask, (unsigned*)pmw);

    // LoRA down: [N,768]@[768,8]
    lora_down_kernel<<<N_ / 8, 256>>>(query, lAq, (float*)pAq);
    lora_down_kernel<<<N_ / 8, 256>>>(value, lAv, (float*)pAv);

    // LoRA up + residual
    lora_up_kernel<<<(N_ * D_) / 256, 256>>>(query, (const float*)pAq, lBq, (float*)pQadj);
    lora_up_kernel<<<(N_ * D_) / 256, 256>>>(value, (const float*)pAv, lBv, (float*)pVadj);

    // Projections (reference's stream swap preserved):
    //   v = heads(Qadj @ Wv^T + bv), k = heads(key @ Wk^T + bk),
    //   q = heads(Vadj @ Wq^T + bq) * (1/sqrt(DK))
    dim3 gg(N_ / 128, D_ / 64);
    gemm_tf32_kernel<<<gg, 128>>>((const float*)pQadj, Wv, bv, (float*)pvh, 1.0f,   1);
    gemm_tf32_kernel<<<gg, 128>>>(key,                 Wk, bk, (float*)pkh, 1.0f,   1);
    gemm_tf32_kernel<<<gg, 128>>>((const float*)pVadj, Wq, bq, (float*)pqh, 0.125f, 1);

    // Flash attention (tensor cores) -> g_ao [B,S,D]
    cudaFuncSetAttribute(attn_tc_kernel, cudaFuncAttributeMaxDynamicSharedMemorySize, ATTN_SMEM);
    attn_tc_kernel<<<dim3(S_ / 128, H_, B_), 128, ATTN_SMEM>>>((const unsigned*)pmw, (float*)pao);

    // Final: out = g_ao @ Wm^T + bm
    gemm_tf32_kernel<<<gg, 128>>>((const float*)pao, Wm, bm, out, 1.0f, 0);
}